// round 15
// baseline (speedup 1.0000x reference)
#include <cuda_runtime.h>
#include <cuda_fp16.h>
#include <cstdint>

#define B_ 128
#define T_ 500
#define M_ 512
#define L_ 128
#define NROWS (B_ * T_)        // 64000

// ---- GEMM tiling (R9-proven config) ----
#define RM 64                  // rows per CTA
#define NC 256                 // interleaved (v,u) cols
#define KC 64                  // K per chunk
#define NCHUNK (M_ / KC)       // 8
#define ASTRIDE 144            // bytes per A row (128B data + 16 pad)
#define BSTRIDE 144

// per-stage smem layout (bytes)
#define A_HI 0
#define B_OFF (RM * ASTRIDE)             // 9216
#define STAGE (B_OFF + NC * BSTRIDE)     // 46080
#define DYN (2 * STAGE)                  // 92160

// ---- persistent device scratch ----
__device__ __half g_Bh[NC * M_];   // interleaved W^T fp16 [256][512]
__device__ float  g_C[NROWS * 2];  // C = H @ Wc  [64000][2]
__device__ int    g_cnt[B_];       // per-bag CTA completion counters

// ============================ helpers ============================
__device__ __forceinline__ uint32_t smem_u32(const void* p) {
    uint32_t a;
    asm("{ .reg .u64 t; cvta.to.shared.u64 t, %1; cvt.u32.u64 %0, t; }" : "=r"(a) : "l"(p));
    return a;
}
// fast gate functions (MUFU ex2-based; ~1e-6 rel err, negligible vs GEMM 3.3e-4)
__device__ __forceinline__ float fast_sigm(float x) {
    return __fdividef(1.0f, 1.0f + __expf(-x));
}
__device__ __forceinline__ float fast_tanh(float x) {
    float t = __expf(2.0f * x);
    return 1.0f - __fdividef(2.0f, t + 1.0f);
}

__device__ __forceinline__ void ldsm_x4(uint32_t (&r)[4], uint32_t addr) {
    asm volatile("ldmatrix.sync.aligned.m8n8.x4.shared.b16 {%0,%1,%2,%3}, [%4];"
                 : "=r"(r[0]), "=r"(r[1]), "=r"(r[2]), "=r"(r[3]) : "r"(addr));
}
__device__ __forceinline__ void mma_f16(float (&c)[4], const uint32_t (&a)[4],
                                        uint32_t b0, uint32_t b1) {
    asm volatile(
        "mma.sync.aligned.m16n8k16.row.col.f32.f16.f16.f32 "
        "{%0,%1,%2,%3}, {%4,%5,%6,%7}, {%8,%9}, {%0,%1,%2,%3};"
        : "+f"(c[0]), "+f"(c[1]), "+f"(c[2]), "+f"(c[3])
        : "r"(a[0]), "r"(a[1]), "r"(a[2]), "r"(a[3]), "r"(b0), "r"(b1));
}
__device__ __forceinline__ uint32_t pack2h(__half a, __half b) {
    unsigned short ra = *(unsigned short*)&a, rb = *(unsigned short*)&b;
    return (uint32_t)ra | ((uint32_t)rb << 16);
}
__device__ __forceinline__ void cpasync16(uint32_t dst, const void* src) {
    asm volatile("cp.async.cg.shared.global [%0], [%1], 16;" :: "r"(dst), "l"(src));
}
#define CP_COMMIT() asm volatile("cp.async.commit_group;" ::: "memory")
#define CP_WAIT0()  asm volatile("cp.async.wait_group 0;" ::: "memory")

// ============================================================================
// prep v4: smem-tiled transpose + counter reset. grid=128 x 256 threads.
//   g_Bh col 2j -> Wv[:,j], col 2j+1 -> Wu[:,j]; each block does 4 k-rows.
// ============================================================================
__global__ void __launch_bounds__(256) prep_kernel(
    const float* __restrict__ Wv, const float* __restrict__ Wu)
{
    __shared__ __half tl[256][6];      // [n][4 k + 2 pad] (12B row stride)
    const int tid = threadIdx.x;
    const int kb = blockIdx.x * 4;

    if (blockIdx.x == 0 && tid < B_) g_cnt[tid] = 0;   // reset bag counters

#pragma unroll
    for (int it = 0; it < 2; it++) {
        int idx = it * 256 + tid;      // 0..511
        int r = idx >> 7, j = idx & 127;
        tl[2 * j][r] = __float2half_rn(Wv[(kb + r) * L_ + j]);
    }
#pragma unroll
    for (int it = 0; it < 2; it++) {
        int idx = it * 256 + tid;
        int r = idx >> 7, j = idx & 127;
        tl[2 * j + 1][r] = __float2half_rn(Wu[(kb + r) * L_ + j]);
    }
    __syncthreads();
    uint32_t w0 = *(const uint32_t*)&tl[tid][0];
    uint32_t w1 = *(const uint32_t*)&tl[tid][2];
    *(uint2*)(g_Bh + tid * M_ + kb) = make_uint2(w0, w1);
}

// ============================================================================
// GEMM (fp16 x fp16 via mma.sync) + fused gate/Wa epilogue + fp32 C=H@Wc
// + fused per-bag softmax/pool (last CTA per bag does it).
// grid = 1000, block = 256 (8 warps: 2 M x 4 N), CTA tile 64 x 256, K = 512
// COMPUTE v2: B-ldmatrix software-pipelined one p-step ahead.
// ============================================================================
__global__ void __launch_bounds__(256, 2) gemm_attn_kernel(
    const float* __restrict__ H,  const float* __restrict__ bv,
    const float* __restrict__ bu, const float* __restrict__ Wa,
    const float* __restrict__ ba, const float* __restrict__ Wc,
    const float* __restrict__ bc,
    float* __restrict__ A_raw, float* __restrict__ A_sm,
    float* __restrict__ out)
{
    extern __shared__ char sm[];
    __shared__ float bvS[L_], buS[L_], WaS[L_];
    __shared__ float Wc0S[M_], Wc1S[M_];
    __shared__ float red[RM][4];
    __shared__ int   do_bag[2];
    __shared__ float pr[8], prB[8];
    __shared__ float sh_mx, sh_sum;

    const int tid  = threadIdx.x;
    const int lane = tid & 31;
    const int warp = tid >> 5;
    const int wm   = warp >> 2;      // 0..1
    const int wn   = warp & 3;       // 0..3
    const size_t n0 = (size_t)blockIdx.x * RM;
    // co-resident CTAs are bid, bid+148 (same LUT slot) -> differ in wave idx
    const int rot = ((blockIdx.x / 148) & 1) << 2;   // 0 or 4
#define CH(c) ((c) ^ rot)

    if (tid < L_) { bvS[tid] = bv[tid]; buS[tid] = bu[tid]; WaS[tid] = Wa[tid]; }
#pragma unroll
    for (int i = 0; i < 2; i++) {
        int k = i * 256 + tid;
        Wc0S[k] = Wc[2 * k];
        Wc1S[k] = Wc[2 * k + 1];
    }

    float acc[2][8][4];
#pragma unroll
    for (int mt = 0; mt < 2; mt++)
#pragma unroll
        for (int nt = 0; nt < 8; nt++)
#pragma unroll
            for (int i = 0; i < 4; i++) acc[mt][nt][i] = 0.0f;

    float4 ar[4];                    // A staging regs (fp32, also feeds C)
    float cc[4][2];                  // fp32 C = H @ Wc accumulators (4 rows)
#pragma unroll
    for (int i = 0; i < 4; i++) { cc[i][0] = 0.0f; cc[i][1] = 0.0f; }

    const uint32_t smb = smem_u32(sm);

    const uint32_t a_ld_row  = (uint32_t)(wm * 32 + (lane & 15));
    const uint32_t a_ld_koff = (uint32_t)((lane >> 4) * 16);
    const uint32_t b_ld_n    = (uint32_t)(wn * 64 + (lane & 7) + ((lane >> 4) << 3));
    const uint32_t b_ld_koff = (uint32_t)(((lane >> 3) & 1) * 16);
    // hoisted per-thread smem base offsets (stage-relative)
    const uint32_t a_base_off = A_HI + a_ld_row * ASTRIDE + a_ld_koff;
    const uint32_t b_base_off = B_OFF + b_ld_n * BSTRIDE + b_ld_koff;

    const int c_f4 = tid & 15;

#define LOADG_A(c)                                                                 \
    {                                                                              \
        const int kt = (c) * KC;                                                   \
        _Pragma("unroll")                                                          \
        for (int i = 0; i < 4; i++) {                                              \
            int idx = i * 256 + tid;                                               \
            int row = idx >> 4, f4 = idx & 15;                                     \
            ar[i] = *(const float4*)(H + (n0 + row) * M_ + kt + f4 * 4);           \
        }                                                                          \
    }

#define C_ACCUM(c)                                                                 \
    {                                                                              \
        const int kb = (c) * KC + c_f4 * 4;                                        \
        float w00 = Wc0S[kb], w01 = Wc0S[kb + 1], w02 = Wc0S[kb + 2], w03 = Wc0S[kb + 3]; \
        float w10 = Wc1S[kb], w11 = Wc1S[kb + 1], w12 = Wc1S[kb + 2], w13 = Wc1S[kb + 3]; \
        _Pragma("unroll")                                                          \
        for (int i = 0; i < 4; i++) {                                              \
            cc[i][0] = fmaf(ar[i].x, w00, cc[i][0]);                               \
            cc[i][0] = fmaf(ar[i].y, w01, cc[i][0]);                               \
            cc[i][0] = fmaf(ar[i].z, w02, cc[i][0]);                               \
            cc[i][0] = fmaf(ar[i].w, w03, cc[i][0]);                               \
            cc[i][1] = fmaf(ar[i].x, w10, cc[i][1]);                               \
            cc[i][1] = fmaf(ar[i].y, w11, cc[i][1]);                               \
            cc[i][1] = fmaf(ar[i].z, w12, cc[i][1]);                               \
            cc[i][1] = fmaf(ar[i].w, w13, cc[i][1]);                               \
        }                                                                          \
    }

#define CPASYNC_B(c, buf)                                                          \
    {                                                                              \
        const int kt = (c) * KC;                                                   \
        const uint32_t db = smb + (buf) * STAGE + B_OFF;                           \
        _Pragma("unroll")                                                          \
        for (int i = 0; i < 8; i++) {                                              \
            int idx = i * 256 + tid;                                               \
            int n = idx >> 3, k16 = idx & 7;                                       \
            cpasync16(db + n * BSTRIDE + k16 * 16, g_Bh + n * M_ + kt + k16 * 8);  \
        }                                                                          \
        CP_COMMIT();                                                               \
    }

#define STORE_A(buf)                                                               \
    {                                                                              \
        char* sb = sm + (buf) * STAGE;                                             \
        _Pragma("unroll")                                                          \
        for (int i = 0; i < 4; i++) {                                              \
            int idx = i * 256 + tid;                                               \
            int row = idx >> 4, f4 = idx & 15;                                     \
            float4 x = ar[i];                                                      \
            __half h0 = __float2half_rn(x.x), h1 = __float2half_rn(x.y);           \
            __half h2 = __float2half_rn(x.z), h3 = __float2half_rn(x.w);           \
            uint32_t off = (uint32_t)(row * ASTRIDE + f4 * 8);                     \
            *(uint2*)(sb + A_HI + off) = make_uint2(pack2h(h0, h1), pack2h(h2, h3)); \
        }                                                                          \
    }

// COMPUTE v2: B ldmatrix double-buffered, prefetched one p-step ahead.
// Between each ldsm and its consuming MMAs there are now 4 HMMAs of
// independent work; prefetch chain crosses ks boundaries (parity aligned).
#define COMPUTE(buf)                                                               \
    {                                                                              \
        const uint32_t a_base = smb + (buf) * STAGE + a_base_off;                  \
        const uint32_t b_base = smb + (buf) * STAGE + b_base_off;                  \
        uint32_t br[2][4];                                                         \
        ldsm_x4(br[0], b_base);                                                    \
        _Pragma("unroll")                                                          \
        for (int ks = 0; ks < 4; ks++) {                                           \
            uint32_t ah[2][4];                                                     \
            ldsm_x4(ah[0], a_base + ks * 32);                                      \
            ldsm_x4(ah[1], a_base + 16 * ASTRIDE + ks * 32);                       \
            _Pragma("unroll")                                                      \
            for (int p = 0; p < 4; p++) {                                          \
                const int cur = p & 1, nxt = cur ^ 1;                              \
                if (p < 3)                                                         \
                    ldsm_x4(br[nxt], b_base + (p + 1) * 16 * BSTRIDE + ks * 32);   \
                else if (ks < 3)                                                   \
                    ldsm_x4(br[nxt], b_base + (ks + 1) * 32);                      \
                mma_f16(acc[0][2 * p],     ah[0], br[cur][0], br[cur][1]);         \
                mma_f16(acc[0][2 * p + 1], ah[0], br[cur][2], br[cur][3]);         \
                mma_f16(acc[1][2 * p],     ah[1], br[cur][0], br[cur][1]);         \
                mma_f16(acc[1][2 * p + 1], ah[1], br[cur][2], br[cur][3]);         \
            }                                                                      \
        }                                                                          \
    }

    // ---- pipelined main loop (chunk order rotated by CH()) ----
    CPASYNC_B(CH(0), 0);
    LOADG_A(CH(0));
    __syncthreads();            // Wc0S/Wc1S ready for C_ACCUM
    C_ACCUM(CH(0));
    STORE_A(0);
    CP_WAIT0();
    __syncthreads();
#pragma unroll 1
    for (int c = 0; c < NCHUNK; c++) {
        const int buf = c & 1;
        if (c + 1 < NCHUNK) {
            CPASYNC_B(CH(c + 1), buf ^ 1);
            LOADG_A(CH(c + 1));
            C_ACCUM(CH(c + 1));
        }
        COMPUTE(buf);
        if (c + 1 < NCHUNK) {
            STORE_A(buf ^ 1);
            CP_WAIT0();
        }
        __syncthreads();
    }

    // ---- C reduce over the 16-lane k-slice groups, write fp32 C ----
#pragma unroll
    for (int i = 0; i < 4; i++) {
#pragma unroll
        for (int o = 1; o < 16; o <<= 1) {
            cc[i][0] += __shfl_xor_sync(~0u, cc[i][0], o);
            cc[i][1] += __shfl_xor_sync(~0u, cc[i][1], o);
        }
    }
    if (c_f4 == 0) {
        int r0 = tid >> 4;     // 0..15
#pragma unroll
        for (int i = 0; i < 4; i++)
            *(float2*)(g_C + (n0 + r0 + 16 * i) * 2) = make_float2(cc[i][0], cc[i][1]);
    }

    // ---- fused epilogue: gate + Wa dot, in-thread (v,u) pairs ----
#pragma unroll
    for (int mt = 0; mt < 2; mt++) {
        float p0 = 0.0f, p1 = 0.0f;
#pragma unroll
        for (int nt = 0; nt < 8; nt++) {
            int j = wn * 32 + nt * 4 + (lane & 3);
            float bvj = bvS[j], buj = buS[j], waj = WaS[j];
            p0 += fast_tanh(acc[mt][nt][0] + bvj) * fast_sigm(acc[mt][nt][1] + buj) * waj;
            p1 += fast_tanh(acc[mt][nt][2] + bvj) * fast_sigm(acc[mt][nt][3] + buj) * waj;
        }
        p0 += __shfl_xor_sync(~0u, p0, 1); p0 += __shfl_xor_sync(~0u, p0, 2);
        p1 += __shfl_xor_sync(~0u, p1, 1); p1 += __shfl_xor_sync(~0u, p1, 2);
        if ((lane & 3) == 0) {
            int r = wm * 32 + mt * 16 + (lane >> 2);
            red[r][wn] = p0;
            red[r + 8][wn] = p1;
        }
    }
    __syncthreads();
    if (tid < RM) {
        float s = red[tid][0] + red[tid][1] + red[tid][2] + red[tid][3] + __ldg(ba);
        A_raw[n0 + tid] = s;
    }

    // ==== fused per-bag pool: last CTA of each bag does softmax+pool ====
    __threadfence();
    __syncthreads();
    if (tid == 0) {
        do_bag[0] = -1; do_bag[1] = -1;
        int bag_lo = (int)(n0 / T_);
        int bag_hi = (int)((n0 + RM - 1) / T_);
        for (int b = bag_lo; b <= bag_hi; b++) {
            int first = (b * T_) / RM;
            int last  = (b * T_ + T_ - 1) / RM;
            int cnt   = last - first + 1;
            if (atomicAdd(&g_cnt[b], 1) == cnt - 1)
                do_bag[b - bag_lo] = b;
        }
    }
    __syncthreads();

#pragma unroll 1
    for (int s = 0; s < 2; s++) {
        int b = do_bag[s];
        if (b < 0) continue;
        const float* Ab = A_raw + b * T_;
        float a0 = (tid < T_) ? Ab[tid] : -1e30f;
        float a1 = (tid + 256 < T_) ? Ab[tid + 256] : -1e30f;
        float mx = fmaxf(a0, a1);
#pragma unroll
        for (int o = 16; o; o >>= 1) mx = fmaxf(mx, __shfl_xor_sync(~0u, mx, o));
        if (lane == 0) pr[warp] = mx;
        __syncthreads();
        if (tid < 32) {
            float v = (tid < 8) ? pr[tid] : -1e30f;
#pragma unroll
            for (int o = 4; o; o >>= 1) v = fmaxf(v, __shfl_xor_sync(~0u, v, o));
            if (tid == 0) sh_mx = v;
        }
        __syncthreads();
        float e0 = (tid < T_) ? __expf(a0 - sh_mx) : 0.0f;
        float e1 = (tid + 256 < T_) ? __expf(a1 - sh_mx) : 0.0f;
        float sum = e0 + e1;
#pragma unroll
        for (int o = 16; o; o >>= 1) sum += __shfl_xor_sync(~0u, sum, o);
        __syncthreads();
        if (lane == 0) pr[warp] = sum;
        __syncthreads();
        if (tid < 32) {
            float v = (tid < 8) ? pr[tid] : 0.0f;
#pragma unroll
            for (int o = 4; o; o >>= 1) v += __shfl_xor_sync(~0u, v, o);
            if (tid == 0) sh_sum = v;
        }
        __syncthreads();
        float inv = __fdividef(1.0f, sh_sum);
        float w0 = e0 * inv, w1 = e1 * inv;
        float c0 = 0.0f, c1 = 0.0f;
        if (tid < T_) {
            A_sm[b * T_ + tid] = w0;
            float2 cv = *(const float2*)(g_C + (b * T_ + tid) * 2);
            c0 = fmaf(w0, cv.x, c0); c1 = fmaf(w0, cv.y, c1);
        }
        if (tid + 256 < T_) {
            A_sm[b * T_ + tid + 256] = w1;
            float2 cv = *(const float2*)(g_C + (b * T_ + tid + 256) * 2);
            c0 = fmaf(w1, cv.x, c0); c1 = fmaf(w1, cv.y, c1);
        }
#pragma unroll
        for (int o = 16; o; o >>= 1) {
            c0 += __shfl_xor_sync(~0u, c0, o);
            c1 += __shfl_xor_sync(~0u, c1, o);
        }
        __syncthreads();
        if (lane == 0) { pr[warp] = c0; prB[warp] = c1; }
        __syncthreads();
        if (tid == 0) {
            float r0 = 0.0f, r1 = 0.0f;
#pragma unroll
            for (int i = 0; i < 8; i++) { r0 += pr[i]; r1 += prB[i]; }
            out[b * 2 + 0] = r0 + bc[0];
            out[b * 2 + 1] = r1 + bc[1];
        }
        __syncthreads();
    }
}

// ============================================================================
// Launch. Output layout: [out (B*2) | A_sm (B*T) | A_t raw logits (B*T)]
// ============================================================================
extern "C" void kernel_launch(void* const* d_in, const int* in_sizes, int n_in,
                              void* d_out, int out_size)
{
    const float* H  = (const float*)d_in[0];
    const float* Wv = (const float*)d_in[1];
    const float* bv = (const float*)d_in[2];
    const float* Wu = (const float*)d_in[3];
    const float* bu = (const float*)d_in[4];
    const float* Wa = (const float*)d_in[5];
    const float* ba = (const float*)d_in[6];
    const float* Wc = (const float*)d_in[7];
    const float* bc = (const float*)d_in[8];

    float* out   = (float*)d_out;
    float* A_sm  = out + B_ * 2;
    float* A_raw = A_sm + B_ * T_;

    cudaFuncSetAttribute(gemm_attn_kernel,
                         cudaFuncAttributeMaxDynamicSharedMemorySize, DYN);

    prep_kernel<<<128, 256>>>(Wv, Wu);
    gemm_attn_kernel<<<NROWS / RM, 256, DYN>>>(H, bv, bu, Wa, ba, Wc, bc,
                                               A_raw, A_sm, out);
}

// round 16
// speedup vs baseline: 1.0137x; 1.0137x over previous
#include <cuda_runtime.h>
#include <cuda_fp16.h>
#include <cstdint>

#define B_ 128
#define T_ 500
#define M_ 512
#define L_ 128
#define NROWS (B_ * T_)        // 64000

// ---- GEMM tiling (R9-proven config) ----
#define RM 64                  // rows per tile
#define NC 256                 // interleaved (v,u) cols
#define KC 64                  // K per chunk
#define NCHUNK (M_ / KC)       // 8
#define ASTRIDE 144            // bytes per A row (128B data + 16 pad)
#define BSTRIDE 144
#define NLONG 112              // CTAs that process 2 tiles (balance 1000 over 296 slots)
#define GRID 888               // 3 x 296 slots exactly

// per-stage smem layout (bytes)
#define A_HI 0
#define B_OFF (RM * ASTRIDE)             // 9216
#define STAGE (B_OFF + NC * BSTRIDE)     // 46080
#define DYN (2 * STAGE)                  // 92160

// ---- persistent device scratch ----
__device__ __half g_Bh[NC * M_];   // interleaved W^T fp16 [256][512]
__device__ float  g_C[NROWS * 2];  // C = H @ Wc  [64000][2]
__device__ int    g_cnt[B_];       // per-bag tile completion counters

// ============================ helpers ============================
__device__ __forceinline__ uint32_t smem_u32(const void* p) {
    uint32_t a;
    asm("{ .reg .u64 t; cvta.to.shared.u64 t, %1; cvt.u32.u64 %0, t; }" : "=r"(a) : "l"(p));
    return a;
}
__device__ __forceinline__ float fast_sigm(float x) {
    return __fdividef(1.0f, 1.0f + __expf(-x));
}
__device__ __forceinline__ float fast_tanh(float x) {
    float t = __expf(2.0f * x);
    return 1.0f - __fdividef(2.0f, t + 1.0f);
}

__device__ __forceinline__ void ldsm_x4(uint32_t (&r)[4], uint32_t addr) {
    asm volatile("ldmatrix.sync.aligned.m8n8.x4.shared.b16 {%0,%1,%2,%3}, [%4];"
                 : "=r"(r[0]), "=r"(r[1]), "=r"(r[2]), "=r"(r[3]) : "r"(addr));
}
__device__ __forceinline__ void mma_f16(float (&c)[4], const uint32_t (&a)[4],
                                        uint32_t b0, uint32_t b1) {
    asm volatile(
        "mma.sync.aligned.m16n8k16.row.col.f32.f16.f16.f32 "
        "{%0,%1,%2,%3}, {%4,%5,%6,%7}, {%8,%9}, {%0,%1,%2,%3};"
        : "+f"(c[0]), "+f"(c[1]), "+f"(c[2]), "+f"(c[3])
        : "r"(a[0]), "r"(a[1]), "r"(a[2]), "r"(a[3]), "r"(b0), "r"(b1));
}
__device__ __forceinline__ uint32_t pack2h(__half a, __half b) {
    unsigned short ra = *(unsigned short*)&a, rb = *(unsigned short*)&b;
    return (uint32_t)ra | ((uint32_t)rb << 16);
}
__device__ __forceinline__ void cpasync16(uint32_t dst, const void* src) {
    asm volatile("cp.async.cg.shared.global [%0], [%1], 16;" :: "r"(dst), "l"(src));
}
#define CP_COMMIT() asm volatile("cp.async.commit_group;" ::: "memory")
#define CP_WAIT0()  asm volatile("cp.async.wait_group 0;" ::: "memory")

// ============================================================================
// prep v4: smem-tiled transpose + counter reset. grid=128 x 256 threads.
// ============================================================================
__global__ void __launch_bounds__(256) prep_kernel(
    const float* __restrict__ Wv, const float* __restrict__ Wu)
{
    __shared__ __half tl[256][6];
    const int tid = threadIdx.x;
    const int kb = blockIdx.x * 4;

    if (blockIdx.x == 0 && tid < B_) g_cnt[tid] = 0;

#pragma unroll
    for (int it = 0; it < 2; it++) {
        int idx = it * 256 + tid;
        int r = idx >> 7, j = idx & 127;
        tl[2 * j][r] = __float2half_rn(Wv[(kb + r) * L_ + j]);
    }
#pragma unroll
    for (int it = 0; it < 2; it++) {
        int idx = it * 256 + tid;
        int r = idx >> 7, j = idx & 127;
        tl[2 * j + 1][r] = __float2half_rn(Wu[(kb + r) * L_ + j]);
    }
    __syncthreads();
    uint32_t w0 = *(const uint32_t*)&tl[tid][0];
    uint32_t w1 = *(const uint32_t*)&tl[tid][2];
    *(uint2*)(g_Bh + tid * M_ + kb) = make_uint2(w0, w1);
}

// ============================================================================
// GEMM (fp16 mma.sync) + gate/Wa epilogue + fp32 C=H@Wc + fused per-bag pool.
// grid = 888: bids 0..111 process 2 row-tiles, 112..887 one. 1000 tiles total.
// Mixed CTA sizes smooth the 3.38-wave integer imbalance (longest-first).
// ============================================================================
__global__ void __launch_bounds__(256, 2) gemm_attn_kernel(
    const float* __restrict__ H,  const float* __restrict__ bv,
    const float* __restrict__ bu, const float* __restrict__ Wa,
    const float* __restrict__ ba, const float* __restrict__ Wc,
    const float* __restrict__ bc,
    float* __restrict__ A_raw, float* __restrict__ A_sm,
    float* __restrict__ out)
{
    extern __shared__ char sm[];
    __shared__ float bvS[L_], buS[L_], WaS[L_];
    __shared__ float Wc0S[M_], Wc1S[M_];
    __shared__ float red[RM][4];
    __shared__ int   do_bag[2];
    __shared__ float pr[8], prB[8];
    __shared__ float sh_mx, sh_sum;

    const int tid  = threadIdx.x;
    const int lane = tid & 31;
    const int warp = tid >> 5;
    const int wm   = warp >> 2;      // 0..1
    const int wn   = warp & 3;       // 0..3
    const int bid  = blockIdx.x;
    const int nsub  = (bid < NLONG) ? 2 : 1;
    const int tile0 = (bid < NLONG) ? (2 * bid) : (NLONG + bid);
    const int rot = ((bid / 148) & 1) << 2;   // 0 or 4 (co-resident desync)
#define CH(c) ((c) ^ rot)

    if (tid < L_) { bvS[tid] = bv[tid]; buS[tid] = bu[tid]; WaS[tid] = Wa[tid]; }
#pragma unroll
    for (int i = 0; i < 2; i++) {
        int k = i * 256 + tid;
        Wc0S[k] = Wc[2 * k];
        Wc1S[k] = Wc[2 * k + 1];
    }

    float acc[2][8][4];
    float4 ar[4];                    // A staging regs (fp32, also feeds C)
    float cc[4][2];                  // fp32 C = H @ Wc accumulators (4 rows)

    const uint32_t smb = smem_u32(sm);

    const uint32_t a_ld_row  = (uint32_t)(wm * 32 + (lane & 15));
    const uint32_t a_ld_koff = (uint32_t)((lane >> 4) * 16);
    const uint32_t b_ld_n    = (uint32_t)(wn * 64 + (lane & 7) + ((lane >> 4) << 3));
    const uint32_t b_ld_koff = (uint32_t)(((lane >> 3) & 1) * 16);
    const uint32_t a_base_off = A_HI + a_ld_row * ASTRIDE + a_ld_koff;
    const uint32_t b_base_off = B_OFF + b_ld_n * BSTRIDE + b_ld_koff;

    const int c_f4 = tid & 15;

#define LOADG_A(c)                                                                 \
    {                                                                              \
        const int kt = (c) * KC;                                                   \
        _Pragma("unroll")                                                          \
        for (int i = 0; i < 4; i++) {                                              \
            int idx = i * 256 + tid;                                               \
            int row = idx >> 4, f4 = idx & 15;                                     \
            ar[i] = *(const float4*)(H + (n0 + row) * M_ + kt + f4 * 4);           \
        }                                                                          \
    }

#define C_ACCUM(c)                                                                 \
    {                                                                              \
        const int kb = (c) * KC + c_f4 * 4;                                        \
        float w00 = Wc0S[kb], w01 = Wc0S[kb + 1], w02 = Wc0S[kb + 2], w03 = Wc0S[kb + 3]; \
        float w10 = Wc1S[kb], w11 = Wc1S[kb + 1], w12 = Wc1S[kb + 2], w13 = Wc1S[kb + 3]; \
        _Pragma("unroll")                                                          \
        for (int i = 0; i < 4; i++) {                                              \
            cc[i][0] = fmaf(ar[i].x, w00, cc[i][0]);                               \
            cc[i][0] = fmaf(ar[i].y, w01, cc[i][0]);                               \
            cc[i][0] = fmaf(ar[i].z, w02, cc[i][0]);                               \
            cc[i][0] = fmaf(ar[i].w, w03, cc[i][0]);                               \
            cc[i][1] = fmaf(ar[i].x, w10, cc[i][1]);                               \
            cc[i][1] = fmaf(ar[i].y, w11, cc[i][1]);                               \
            cc[i][1] = fmaf(ar[i].z, w12, cc[i][1]);                               \
            cc[i][1] = fmaf(ar[i].w, w13, cc[i][1]);                               \
        }                                                                          \
    }

#define CPASYNC_B(c, buf)                                                          \
    {                                                                              \
        const int kt = (c) * KC;                                                   \
        const uint32_t db = smb + (buf) * STAGE + B_OFF;                           \
        _Pragma("unroll")                                                          \
        for (int i = 0; i < 8; i++) {                                              \
            int idx = i * 256 + tid;                                               \
            int n = idx >> 3, k16 = idx & 7;                                       \
            cpasync16(db + n * BSTRIDE + k16 * 16, g_Bh + n * M_ + kt + k16 * 8);  \
        }                                                                          \
        CP_COMMIT();                                                               \
    }

#define STORE_A(buf)                                                               \
    {                                                                              \
        char* sb = sm + (buf) * STAGE;                                             \
        _Pragma("unroll")                                                          \
        for (int i = 0; i < 4; i++) {                                              \
            int idx = i * 256 + tid;                                               \
            int row = idx >> 4, f4 = idx & 15;                                     \
            float4 x = ar[i];                                                      \
            __half h0 = __float2half_rn(x.x), h1 = __float2half_rn(x.y);           \
            __half h2 = __float2half_rn(x.z), h3 = __float2half_rn(x.w);           \
            uint32_t off = (uint32_t)(row * ASTRIDE + f4 * 8);                     \
            *(uint2*)(sb + A_HI + off) = make_uint2(pack2h(h0, h1), pack2h(h2, h3)); \
        }                                                                          \
    }

#define COMPUTE(buf)                                                               \
    {                                                                              \
        const uint32_t a_base = smb + (buf) * STAGE + a_base_off;                  \
        const uint32_t b_base = smb + (buf) * STAGE + b_base_off;                  \
        uint32_t br[2][4];                                                         \
        ldsm_x4(br[0], b_base);                                                    \
        _Pragma("unroll")                                                          \
        for (int ks = 0; ks < 4; ks++) {                                           \
            uint32_t ah[2][4];                                                     \
            ldsm_x4(ah[0], a_base + ks * 32);                                      \
            ldsm_x4(ah[1], a_base + 16 * ASTRIDE + ks * 32);                       \
            _Pragma("unroll")                                                      \
            for (int p = 0; p < 4; p++) {                                          \
                const int cur = p & 1, nxt = cur ^ 1;                              \
                if (p < 3)                                                         \
                    ldsm_x4(br[nxt], b_base + (p + 1) * 16 * BSTRIDE + ks * 32);   \
                else if (ks < 3)                                                   \
                    ldsm_x4(br[nxt], b_base + (ks + 1) * 32);                      \
                mma_f16(acc[0][2 * p],     ah[0], br[cur][0], br[cur][1]);         \
                mma_f16(acc[0][2 * p + 1], ah[0], br[cur][2], br[cur][3]);         \
                mma_f16(acc[1][2 * p],     ah[1], br[cur][0], br[cur][1]);         \
                mma_f16(acc[1][2 * p + 1], ah[1], br[cur][2], br[cur][3]);         \
            }                                                                      \
        }                                                                          \
    }

#pragma unroll 1
    for (int sub = 0; sub < nsub; sub++) {
        const size_t n0 = (size_t)(tile0 + sub) * RM;

#pragma unroll
        for (int mt = 0; mt < 2; mt++)
#pragma unroll
            for (int nt = 0; nt < 8; nt++)
#pragma unroll
                for (int i = 0; i < 4; i++) acc[mt][nt][i] = 0.0f;
#pragma unroll
        for (int i = 0; i < 4; i++) { cc[i][0] = 0.0f; cc[i][1] = 0.0f; }

        // ---- pipelined main loop (chunk order rotated by CH()) ----
        CPASYNC_B(CH(0), 0);
        LOADG_A(CH(0));
        __syncthreads();            // Wc0S/Wc1S ready (sub 0) / prior sub done
        C_ACCUM(CH(0));
        STORE_A(0);
        CP_WAIT0();
        __syncthreads();
#pragma unroll 1
        for (int c = 0; c < NCHUNK; c++) {
            const int buf = c & 1;
            if (c + 1 < NCHUNK) {
                CPASYNC_B(CH(c + 1), buf ^ 1);
                LOADG_A(CH(c + 1));
                C_ACCUM(CH(c + 1));
            }
            COMPUTE(buf);
            if (c + 1 < NCHUNK) {
                STORE_A(buf ^ 1);
                CP_WAIT0();
            }
            __syncthreads();
        }

        // ---- C reduce over the 16-lane k-slice groups, write fp32 C ----
#pragma unroll
        for (int i = 0; i < 4; i++) {
#pragma unroll
            for (int o = 1; o < 16; o <<= 1) {
                cc[i][0] += __shfl_xor_sync(~0u, cc[i][0], o);
                cc[i][1] += __shfl_xor_sync(~0u, cc[i][1], o);
            }
        }
        if (c_f4 == 0) {
            int r0 = tid >> 4;     // 0..15
#pragma unroll
            for (int i = 0; i < 4; i++)
                *(float2*)(g_C + (n0 + r0 + 16 * i) * 2) = make_float2(cc[i][0], cc[i][1]);
        }

        // ---- fused epilogue: gate + Wa dot, in-thread (v,u) pairs ----
#pragma unroll
        for (int mt = 0; mt < 2; mt++) {
            float p0 = 0.0f, p1 = 0.0f;
#pragma unroll
            for (int nt = 0; nt < 8; nt++) {
                int j = wn * 32 + nt * 4 + (lane & 3);
                float bvj = bvS[j], buj = buS[j], waj = WaS[j];
                p0 += fast_tanh(acc[mt][nt][0] + bvj) * fast_sigm(acc[mt][nt][1] + buj) * waj;
                p1 += fast_tanh(acc[mt][nt][2] + bvj) * fast_sigm(acc[mt][nt][3] + buj) * waj;
            }
            p0 += __shfl_xor_sync(~0u, p0, 1); p0 += __shfl_xor_sync(~0u, p0, 2);
            p1 += __shfl_xor_sync(~0u, p1, 1); p1 += __shfl_xor_sync(~0u, p1, 2);
            if ((lane & 3) == 0) {
                int r = wm * 32 + mt * 16 + (lane >> 2);
                red[r][wn] = p0;
                red[r + 8][wn] = p1;
            }
        }
        __syncthreads();
        if (tid < RM) {
            float s = red[tid][0] + red[tid][1] + red[tid][2] + red[tid][3] + __ldg(ba);
            A_raw[n0 + tid] = s;
        }

        // ==== fused per-bag pool: last tile of each bag does softmax+pool ====
        __threadfence();
        __syncthreads();
        if (tid == 0) {
            do_bag[0] = -1; do_bag[1] = -1;
            int bag_lo = (int)(n0 / T_);
            int bag_hi = (int)((n0 + RM - 1) / T_);
            for (int b = bag_lo; b <= bag_hi; b++) {
                int first = (b * T_) / RM;
                int last  = (b * T_ + T_ - 1) / RM;
                int cnt   = last - first + 1;
                if (atomicAdd(&g_cnt[b], 1) == cnt - 1)
                    do_bag[b - bag_lo] = b;
            }
        }
        __syncthreads();

#pragma unroll 1
        for (int s = 0; s < 2; s++) {
            int b = do_bag[s];
            if (b < 0) continue;
            const float* Ab = A_raw + b * T_;
            float a0 = (tid < T_) ? Ab[tid] : -1e30f;
            float a1 = (tid + 256 < T_) ? Ab[tid + 256] : -1e30f;
            float mx = fmaxf(a0, a1);
#pragma unroll
            for (int o = 16; o; o >>= 1) mx = fmaxf(mx, __shfl_xor_sync(~0u, mx, o));
            if (lane == 0) pr[warp] = mx;
            __syncthreads();
            if (tid < 32) {
                float v = (tid < 8) ? pr[tid] : -1e30f;
#pragma unroll
                for (int o = 4; o; o >>= 1) v = fmaxf(v, __shfl_xor_sync(~0u, v, o));
                if (tid == 0) sh_mx = v;
            }
            __syncthreads();
            float e0 = (tid < T_) ? __expf(a0 - sh_mx) : 0.0f;
            float e1 = (tid + 256 < T_) ? __expf(a1 - sh_mx) : 0.0f;
            float sum = e0 + e1;
#pragma unroll
            for (int o = 16; o; o >>= 1) sum += __shfl_xor_sync(~0u, sum, o);
            __syncthreads();
            if (lane == 0) pr[warp] = sum;
            __syncthreads();
            if (tid < 32) {
                float v = (tid < 8) ? pr[tid] : 0.0f;
#pragma unroll
                for (int o = 4; o; o >>= 1) v += __shfl_xor_sync(~0u, v, o);
                if (tid == 0) sh_sum = v;
            }
            __syncthreads();
            float inv = __fdividef(1.0f, sh_sum);
            float w0 = e0 * inv, w1 = e1 * inv;
            float c0 = 0.0f, c1 = 0.0f;
            if (tid < T_) {
                A_sm[b * T_ + tid] = w0;
                float2 cv = *(const float2*)(g_C + (b * T_ + tid) * 2);
                c0 = fmaf(w0, cv.x, c0); c1 = fmaf(w0, cv.y, c1);
            }
            if (tid + 256 < T_) {
                A_sm[b * T_ + tid + 256] = w1;
                float2 cv = *(const float2*)(g_C + (b * T_ + tid + 256) * 2);
                c0 = fmaf(w1, cv.x, c0); c1 = fmaf(w1, cv.y, c1);
            }
#pragma unroll
            for (int o = 16; o; o >>= 1) {
                c0 += __shfl_xor_sync(~0u, c0, o);
                c1 += __shfl_xor_sync(~0u, c1, o);
            }
            __syncthreads();
            if (lane == 0) { pr[warp] = c0; prB[warp] = c1; }
            __syncthreads();
            if (tid == 0) {
                float r0 = 0.0f, r1 = 0.0f;
#pragma unroll
                for (int i = 0; i < 8; i++) { r0 += pr[i]; r1 += prB[i]; }
                out[b * 2 + 0] = r0 + bc[0];
                out[b * 2 + 1] = r1 + bc[1];
            }
            __syncthreads();
        }
    }
}

// ============================================================================
// Launch. Output layout: [out (B*2) | A_sm (B*T) | A_t raw logits (B*T)]
// ============================================================================
extern "C" void kernel_launch(void* const* d_in, const int* in_sizes, int n_in,
                              void* d_out, int out_size)
{
    const float* H  = (const float*)d_in[0];
    const float* Wv = (const float*)d_in[1];
    const float* bv = (const float*)d_in[2];
    const float* Wu = (const float*)d_in[3];
    const float* bu = (const float*)d_in[4];
    const float* Wa = (const float*)d_in[5];
    const float* ba = (const float*)d_in[6];
    const float* Wc = (const float*)d_in[7];
    const float* bc = (const float*)d_in[8];

    float* out   = (float*)d_out;
    float* A_sm  = out + B_ * 2;
    float* A_raw = A_sm + B_ * T_;

    cudaFuncSetAttribute(gemm_attn_kernel,
                         cudaFuncAttributeMaxDynamicSharedMemorySize, DYN);

    prep_kernel<<<128, 256>>>(Wv, Wu);
    gemm_attn_kernel<<<GRID, 256, DYN>>>(H, bv, bu, Wa, ba, Wc, bc,
                                         A_raw, A_sm, out);
}